// round 8
// baseline (speedup 1.0000x reference)
#include <cuda_runtime.h>
#include <cuda_bf16.h>
#include <cstdint>

// q[n,k] = (1/(1+dist(n,k))) / rowsum,  dist = ||x||^2+||c||^2-2 x.c
// N=65536, K=256, D=512, fp32 in/out. ALPHA=1 -> exponent exactly 1.
#define NROWS 65536
#define KCL   256
#define DDIM  512
#define BM    32           // rows per CTA (tiny tile -> 3 CTAs/SM)
#define DC    64           // bf16 K-cols per stage
#define NCH   (DDIM / DC)  // 8

// SMEM (bytes). Tiles have 128B rows (8 x 16B chunks), XOR-swizzled.
// A: 2 stages x 4KB. B: 2 stages x 32KB.
#define SOFF_A0   0
#define SOFF_A1   4096
#define SOFF_B0   8192
#define SOFF_B1   40960
#define SOFF_X2   73728      // 32 f
#define SOFF_C2   73856      // 256 f
#define SOFF_RS   74880      // 8*32 f
#define SMEM_BYTES 75904

#define B_ROW_BYTES (DDIM * 2)   // 1024 B per cluster row in g_Bbf

// Pre-converted bf16 clusters + exact fp32 cluster norms (device scratch).
__device__ __align__(16) __nv_bfloat16 g_Bbf[KCL * DDIM];
__device__ float g_c2[KCL];

static __device__ __forceinline__ uint32_t smem_u32(const void* p) {
    uint32_t a;
    asm("{ .reg .u64 t; cvta.to.shared.u64 t, %1; cvt.u32.u64 %0, t; }"
        : "=r"(a) : "l"(p));
    return a;
}
static __device__ __forceinline__ uint32_t packbf(float a, float b) {
    __nv_bfloat162 h = __floats2bfloat162_rn(a, b);
    return *reinterpret_cast<uint32_t*>(&h);
}
static __device__ __forceinline__ void sts64(uint32_t addr, uint32_t p0, uint32_t p1) {
    asm volatile("st.shared.v2.b32 [%0], {%1, %2};"
                 :: "r"(addr), "r"(p0), "r"(p1) : "memory");
}
static __device__ __forceinline__ void cpasync16(uint32_t dst, const void* src) {
    asm volatile("cp.async.cg.shared.global [%0], [%1], 16;"
                 :: "r"(dst), "l"(__cvta_generic_to_global(src)) : "memory");
}
static __device__ __forceinline__ void cp_commit() {
    asm volatile("cp.async.commit_group;" ::: "memory");
}
template <int N>
static __device__ __forceinline__ void cp_wait() {
    asm volatile("cp.async.wait_group %0;" :: "n"(N) : "memory");
}
// 128B-row tile: 16B chunk col cc (0..7) of row r at r*128 + 16*(cc ^ (r&7)).
static __device__ __forceinline__ uint32_t swz(uint32_t row, uint32_t cc) {
    return row * 128u + 16u * (cc ^ (row & 7u));
}
static __device__ __forceinline__ void ldmx4(uint32_t addr, uint32_t& r0, uint32_t& r1,
                                             uint32_t& r2, uint32_t& r3) {
    asm volatile("ldmatrix.sync.aligned.m8n8.x4.shared.b16 {%0,%1,%2,%3}, [%4];"
                 : "=r"(r0), "=r"(r1), "=r"(r2), "=r"(r3) : "r"(addr));
}
static __device__ __forceinline__ void mma16816(float* c, const uint32_t* a,
                                                uint32_t b0, uint32_t b1) {
    asm volatile(
        "mma.sync.aligned.m16n8k16.row.col.f32.bf16.bf16.f32 "
        "{%0,%1,%2,%3}, {%4,%5,%6,%7}, {%8,%9}, {%0,%1,%2,%3};"
        : "+f"(c[0]), "+f"(c[1]), "+f"(c[2]), "+f"(c[3])
        : "r"(a[0]), "r"(a[1]), "r"(a[2]), "r"(a[3]), "r"(b0), "r"(b1));
}

// ---------------- pre-kernel: clusters fp32 -> bf16 + c2 norms ----------------
__global__ void conv_b_kernel(const float* __restrict__ Cc)
{
    const int row = blockIdx.x;       // 256
    const int tid = threadIdx.x;      // 128
    float4 v = reinterpret_cast<const float4*>(Cc + (size_t)row * DDIM)[tid];
    float n = v.x * v.x + v.y * v.y + v.z * v.z + v.w * v.w;
    uint2 p = make_uint2(packbf(v.x, v.y), packbf(v.z, v.w));
    *reinterpret_cast<uint2*>(
        reinterpret_cast<char*>(g_Bbf) + (size_t)row * B_ROW_BYTES + tid * 8) = p;
    n += __shfl_xor_sync(0xffffffffu, n, 16);
    n += __shfl_xor_sync(0xffffffffu, n, 8);
    n += __shfl_xor_sync(0xffffffffu, n, 4);
    n += __shfl_xor_sync(0xffffffffu, n, 2);
    n += __shfl_xor_sync(0xffffffffu, n, 1);
    __shared__ float s[4];
    if ((tid & 31) == 0) s[tid >> 5] = n;
    __syncthreads();
    if (tid == 0) g_c2[row] = s[0] + s[1] + s[2] + s[3];
}

// ---------------------------------- main ----------------------------------
// 256 threads = 8 warps; warp grid 1(m) x 8(n); warp tile 32 rows x 32 cols.
// __launch_bounds__(256, 3): cap regs (<=84) -> 3 CTAs per SM.
__global__ __launch_bounds__(256, 3)
void cluster_q_kernel(const float* __restrict__ X, float* __restrict__ Out)
{
    extern __shared__ char smem[];
    const uint32_t sb = smem_u32(smem);
    const int t     = threadIdx.x;
    const int lane  = t & 31;
    const int warp  = t >> 5;          // warp_n: 32-col block 0..7
    const int m0    = blockIdx.x * BM;

    // ---- A loader: 8 threads per fp32 row (64 floats/chunk), 32 rows, 1 pass.
    const int arow = t >> 3;           // 0..31
    const int au   = t & 7;            // two 16B units: au and au+8
    const float* Asrc = X + (size_t)(m0 + arow) * DDIM;
    const uint32_t aHalf = (uint32_t)(au & 1) * 8u;
    const uint32_t aSt0 = swz((uint32_t)arow, (uint32_t)(au >> 1)) + aHalf;
    const uint32_t aSt1 = swz((uint32_t)arow, (uint32_t)(au >> 1) + 4u) + aHalf;

    // ---- B loader: 8 threads per 128B bf16 row-chunk, 8 passes of 32 rows.
    const int brow = t >> 3;           // 0..31
    const int bcc  = t & 7;
    const char* Bsrc = reinterpret_cast<const char*>(g_Bbf)
                     + (size_t)brow * B_ROW_BYTES + bcc * 16;
    const uint32_t bSt = swz((uint32_t)brow, (uint32_t)bcc);

    float nA = 0.f;
    float acc[2][4][4];
    #pragma unroll
    for (int i = 0; i < 2; ++i)
        #pragma unroll
        for (int j = 0; j < 4; ++j)
            #pragma unroll
            for (int k = 0; k < 4; ++k) acc[i][j][k] = 0.f;

    float4 pa[2];   // A prefetch: 8 floats

    auto G2R = [&](int ch) {
        pa[0] = *reinterpret_cast<const float4*>(Asrc + ch * DC + au * 4);
        pa[1] = *reinterpret_cast<const float4*>(Asrc + ch * DC + (au + 8) * 4);
    };
    auto R2S = [&](int s) {
        const uint32_t aT = sb + (s ? SOFF_A1 : SOFF_A0);
        nA += pa[0].x * pa[0].x + pa[0].y * pa[0].y
            + pa[0].z * pa[0].z + pa[0].w * pa[0].w
            + pa[1].x * pa[1].x + pa[1].y * pa[1].y
            + pa[1].z * pa[1].z + pa[1].w * pa[1].w;
        sts64(aT + aSt0, packbf(pa[0].x, pa[0].y), packbf(pa[0].z, pa[0].w));
        sts64(aT + aSt1, packbf(pa[1].x, pa[1].y), packbf(pa[1].z, pa[1].w));
    };
    auto CPB = [&](int ch) {   // async-copy B chunk ch into stage ch&1
        const uint32_t bT = sb + ((ch & 1) ? SOFF_B1 : SOFF_B0);
        const size_t off = (size_t)ch * 128;   // 128B chunk inside 1024B row
        #pragma unroll
        for (int p = 0; p < 8; ++p)
            cpasync16(bT + bSt + (uint32_t)p * 32u * 128u,
                      Bsrc + (size_t)p * 32 * B_ROW_BYTES + off);
        cp_commit();
    };

    // ldmatrix constant addressing
    const uint32_t aRowBase = (uint32_t)(lane & 15);
    const uint32_t aCCoff   = (uint32_t)(lane >> 4);
    const uint32_t bRowBase = (uint32_t)(warp * 32 + (lane & 7) + ((lane >> 4) << 3));
    const uint32_t bCCoff   = (uint32_t)((lane >> 3) & 1);

    auto COMPUTE = [&](int ch) {
        const uint32_t aT = sb + ((ch & 1) ? SOFF_A1 : SOFF_A0);
        const uint32_t bT = sb + ((ch & 1) ? SOFF_B1 : SOFF_B0);
        #pragma unroll
        for (int ks = 0; ks < 4; ++ks) {
            const uint32_t ccA = (uint32_t)(ks * 2) + aCCoff;
            const uint32_t ccB = (uint32_t)(ks * 2) + bCCoff;
            uint32_t af[2][4];
            #pragma unroll
            for (int mi = 0; mi < 2; ++mi)
                ldmx4(aT + swz(aRowBase + mi * 16, ccA),
                      af[mi][0], af[mi][1], af[mi][2], af[mi][3]);
            #pragma unroll
            for (int nb = 0; nb < 2; ++nb) {
                uint32_t b0, b1, b2, b3;
                ldmx4(bT + swz(bRowBase + nb * 16, ccB), b0, b1, b2, b3);
                #pragma unroll
                for (int mi = 0; mi < 2; ++mi) {
                    mma16816(acc[mi][2 * nb + 0], af[mi], b0, b1);
                    mma16816(acc[mi][2 * nb + 1], af[mi], b2, b3);
                }
            }
        }
    };

    // -------- prologue --------
    CPB(0);
    G2R(0); R2S(0);
    G2R(1);
    cp_wait<0>();
    __syncthreads();

    // -------- mainloop: one sync per chunk; copy ch+1 runs during COMPUTE(ch) ----
    #pragma unroll 1
    for (int ch = 0; ch < NCH; ++ch) {
        if (ch + 1 < NCH) CPB(ch + 1);
        if (ch + 1 < NCH) R2S((ch + 1) & 1);
        if (ch + 2 < NCH) G2R(ch + 2);
        COMPUTE(ch);
        cp_wait<0>();
        __syncthreads();
    }

    // -------- norms --------
    float* x2s = reinterpret_cast<float*>(smem + SOFF_X2);
    float* c2s = reinterpret_cast<float*>(smem + SOFF_C2);
    {
        float v = nA;
        v += __shfl_xor_sync(0xffffffffu, v, 1);
        v += __shfl_xor_sync(0xffffffffu, v, 2);
        v += __shfl_xor_sync(0xffffffffu, v, 4);
        if ((lane & 7) == 0) x2s[arow] = v;
    }
    c2s[t] = g_c2[t];
    __syncthreads();

    // -------- epilogue pass 1: q = 1/(1+dist), row partial sums --------
    const int rbase = lane >> 2;       // 0..7
    float qs[2][2] = {{0.f, 0.f}, {0.f, 0.f}};
    #pragma unroll
    for (int mi = 0; mi < 2; ++mi) {
        const float x2a = x2s[rbase + mi * 16];
        const float x2b = x2s[rbase + mi * 16 + 8];
        #pragma unroll
        for (int ni = 0; ni < 4; ++ni) {
            const int col = warp * 32 + ni * 8 + (lane & 3) * 2;
            const float c2a = c2s[col], c2b = c2s[col + 1];
            float q0 = __fdividef(1.f, 1.f + fmaxf(x2a + c2a - 2.f * acc[mi][ni][0], 0.f));
            float q1 = __fdividef(1.f, 1.f + fmaxf(x2a + c2b - 2.f * acc[mi][ni][1], 0.f));
            float q2 = __fdividef(1.f, 1.f + fmaxf(x2b + c2a - 2.f * acc[mi][ni][2], 0.f));
            float q3 = __fdividef(1.f, 1.f + fmaxf(x2b + c2b - 2.f * acc[mi][ni][3], 0.f));
            acc[mi][ni][0] = q0; acc[mi][ni][1] = q1;
            acc[mi][ni][2] = q2; acc[mi][ni][3] = q3;
            qs[mi][0] += q0 + q1;
            qs[mi][1] += q2 + q3;
        }
    }
    float* rs = reinterpret_cast<float*>(smem + SOFF_RS);
    #pragma unroll
    for (int mi = 0; mi < 2; ++mi) {
        #pragma unroll
        for (int h = 0; h < 2; ++h) {
            float v = qs[mi][h];
            v += __shfl_xor_sync(0xffffffffu, v, 1);
            v += __shfl_xor_sync(0xffffffffu, v, 2);
            if ((lane & 3) == 0)
                rs[warp * 32 + rbase + mi * 16 + h * 8] = v;
        }
    }
    __syncthreads();

    // -------- epilogue pass 2: scale + store --------
    #pragma unroll
    for (int mi = 0; mi < 2; ++mi) {
        #pragma unroll
        for (int h = 0; h < 2; ++h) {
            const int r = rbase + mi * 16 + h * 8;
            float s = 0.f;
            #pragma unroll
            for (int w = 0; w < 8; ++w) s += rs[w * 32 + r];
            const float inv = __fdividef(1.f, s);
            float* orow = Out + (size_t)(m0 + r) * KCL + warp * 32 + (lane & 3) * 2;
            #pragma unroll
            for (int ni = 0; ni < 4; ++ni) {
                float2 v;
                v.x = acc[mi][ni][2 * h + 0] * inv;
                v.y = acc[mi][ni][2 * h + 1] * inv;
                *reinterpret_cast<float2*>(orow + ni * 8) = v;
            }
        }
    }
}

extern "C" void kernel_launch(void* const* d_in, const int* in_sizes, int n_in,
                              void* d_out, int out_size)
{
    const float* X  = (const float*)d_in[0];
    const float* Cc = (const float*)d_in[1];
    if (n_in >= 2 && in_sizes[0] < in_sizes[1]) {   // X is the big tensor
        const float* tmp = X; X = Cc; Cc = tmp;
    }
    float* Out = (float*)d_out;

    static int smem_set = 0;
    if (!smem_set) {
        cudaFuncSetAttribute(cluster_q_kernel,
                             cudaFuncAttributeMaxDynamicSharedMemorySize, SMEM_BYTES);
        smem_set = 1;
    }
    conv_b_kernel<<<KCL, 128>>>(Cc);
    cluster_q_kernel<<<NROWS / BM, 256, SMEM_BYTES>>>(X, Out);
}

// round 9
// speedup vs baseline: 1.1995x; 1.1995x over previous
#include <cuda_runtime.h>
#include <cuda_bf16.h>
#include <cstdint>

// q[n,k] = (1/(1+dist(n,k))) / rowsum,  dist = ||x||^2+||c||^2-2 x.c
// N=65536, K=256, D=512, fp32 in/out. ALPHA=1 -> exponent exactly 1.
#define NROWS 65536
#define KCL   256
#define DDIM  512
#define BM    64           // rows per CTA
#define DC    64           // bf16 K-cols per stage
#define NCH   (DDIM / DC)  // 8

// SMEM (bytes). Tiles have 128B rows (8 x 16B chunks), XOR-swizzled.
// A: 2 stages x 8KB. B: 2 stages x 32KB.
#define SOFF_A0   0
#define SOFF_A1   8192
#define SOFF_B0   16384
#define SOFF_B1   49152
#define SOFF_X2   81920      // 64 f
#define SOFF_C2   82176      // 256 f
#define SOFF_RS   83200      // 4*64 f
#define SMEM_BYTES 84224

#define B_ROW_BYTES (DDIM * 2)   // 1024 B per cluster row in g_Bbf

// Pre-converted bf16 clusters + exact fp32 cluster norms (device scratch).
__device__ __align__(16) __nv_bfloat16 g_Bbf[KCL * DDIM];
__device__ float g_c2[KCL];

static __device__ __forceinline__ uint32_t smem_u32(const void* p) {
    uint32_t a;
    asm("{ .reg .u64 t; cvta.to.shared.u64 t, %1; cvt.u32.u64 %0, t; }"
        : "=r"(a) : "l"(p));
    return a;
}
static __device__ __forceinline__ uint32_t packbf(float a, float b) {
    __nv_bfloat162 h = __floats2bfloat162_rn(a, b);
    return *reinterpret_cast<uint32_t*>(&h);
}
static __device__ __forceinline__ void sts64(uint32_t addr, uint32_t p0, uint32_t p1) {
    asm volatile("st.shared.v2.b32 [%0], {%1, %2};"
                 :: "r"(addr), "r"(p0), "r"(p1) : "memory");
}
static __device__ __forceinline__ void cpasync16(uint32_t dst, const void* src) {
    asm volatile("cp.async.cg.shared.global [%0], [%1], 16;"
                 :: "r"(dst), "l"(__cvta_generic_to_global(src)) : "memory");
}
static __device__ __forceinline__ void cp_commit() {
    asm volatile("cp.async.commit_group;" ::: "memory");
}
template <int N>
static __device__ __forceinline__ void cp_wait() {
    asm volatile("cp.async.wait_group %0;" :: "n"(N) : "memory");
}
// 128B-row tile: 16B chunk col cc (0..7) of row r at r*128 + 16*(cc ^ (r&7)).
static __device__ __forceinline__ uint32_t swz(uint32_t row, uint32_t cc) {
    return row * 128u + 16u * (cc ^ (row & 7u));
}
static __device__ __forceinline__ void ldmx4(uint32_t addr, uint32_t& r0, uint32_t& r1,
                                             uint32_t& r2, uint32_t& r3) {
    asm volatile("ldmatrix.sync.aligned.m8n8.x4.shared.b16 {%0,%1,%2,%3}, [%4];"
                 : "=r"(r0), "=r"(r1), "=r"(r2), "=r"(r3) : "r"(addr));
}
static __device__ __forceinline__ void mma16816(float* c, const uint32_t* a,
                                                uint32_t b0, uint32_t b1) {
    asm volatile(
        "mma.sync.aligned.m16n8k16.row.col.f32.bf16.bf16.f32 "
        "{%0,%1,%2,%3}, {%4,%5,%6,%7}, {%8,%9}, {%0,%1,%2,%3};"
        : "+f"(c[0]), "+f"(c[1]), "+f"(c[2]), "+f"(c[3])
        : "r"(a[0]), "r"(a[1]), "r"(a[2]), "r"(a[3]), "r"(b0), "r"(b1));
}

// ---------------- pre-kernel: clusters fp32 -> bf16 + c2 norms ----------------
__global__ void conv_b_kernel(const float* __restrict__ Cc)
{
    const int row = blockIdx.x;       // 256
    const int tid = threadIdx.x;      // 128
    float4 v = reinterpret_cast<const float4*>(Cc + (size_t)row * DDIM)[tid];
    float n = v.x * v.x + v.y * v.y + v.z * v.z + v.w * v.w;
    uint2 p = make_uint2(packbf(v.x, v.y), packbf(v.z, v.w));
    *reinterpret_cast<uint2*>(
        reinterpret_cast<char*>(g_Bbf) + (size_t)row * B_ROW_BYTES + tid * 8) = p;
    n += __shfl_xor_sync(0xffffffffu, n, 16);
    n += __shfl_xor_sync(0xffffffffu, n, 8);
    n += __shfl_xor_sync(0xffffffffu, n, 4);
    n += __shfl_xor_sync(0xffffffffu, n, 2);
    n += __shfl_xor_sync(0xffffffffu, n, 1);
    __shared__ float s[4];
    if ((tid & 31) == 0) s[tid >> 5] = n;
    __syncthreads();
    if (tid == 0) g_c2[row] = s[0] + s[1] + s[2] + s[3];
}

// ---------------------------------- main ----------------------------------
// 128 threads = 4 warps; warp grid 1(m) x 4(n); warp tile 64 rows x 64 cols.
// __launch_bounds__(128, 2): 2 CTAs per SM (8 warps), reg cap 256 -> no spills.
__global__ __launch_bounds__(128, 2)
void cluster_q_kernel(const float* __restrict__ X, float* __restrict__ Out)
{
    extern __shared__ char smem[];
    const uint32_t sb = smem_u32(smem);
    const int t     = threadIdx.x;
    const int lane  = t & 31;
    const int warp  = t >> 5;          // warp_n: 64-col block 0..3
    const int m0    = blockIdx.x * BM;

    // ---- A loader: 16 threads per row-chunk (64 floats), 8 passes of 8 rows.
    const int arow = t >> 4;           // 0..7
    const int acol = t & 15;           // 16B unit (4 floats)
    const float* Asrc = X + (size_t)(m0 + arow) * DDIM + acol * 4;
    const uint32_t aCC   = (uint32_t)(acol >> 1);
    const uint32_t aHalf = (uint32_t)(acol & 1) * 8u;

    // ---- B loader: 8 threads per 128B bf16 row-chunk, 16 passes of 16 rows.
    const int brow = t >> 3;           // 0..15
    const int bcc  = t & 7;
    const char* Bsrc = reinterpret_cast<const char*>(g_Bbf)
                     + (size_t)brow * B_ROW_BYTES + bcc * 16;
    const uint32_t bSt = swz((uint32_t)brow, (uint32_t)bcc);

    float nAp[8];
    #pragma unroll
    for (int p = 0; p < 8; ++p) nAp[p] = 0.f;

    float acc[4][8][4];
    #pragma unroll
    for (int i = 0; i < 4; ++i)
        #pragma unroll
        for (int j = 0; j < 8; ++j)
            #pragma unroll
            for (int k = 0; k < 4; ++k) acc[i][j][k] = 0.f;

    float4 pa[8];   // A prefetch: one float4 per pass-row (32 regs)

    auto G2R = [&](int ch) {
        #pragma unroll
        for (int p = 0; p < 8; ++p)
            pa[p] = *reinterpret_cast<const float4*>(Asrc + (size_t)p * 8 * DDIM + ch * DC);
    };
    auto R2S = [&](int s) {
        const uint32_t aT = sb + (s ? SOFF_A1 : SOFF_A0);
        #pragma unroll
        for (int p = 0; p < 8; ++p) {
            nAp[p] += pa[p].x * pa[p].x + pa[p].y * pa[p].y
                    + pa[p].z * pa[p].z + pa[p].w * pa[p].w;
            sts64(aT + swz((uint32_t)(arow + 8 * p), aCC) + aHalf,
                  packbf(pa[p].x, pa[p].y), packbf(pa[p].z, pa[p].w));
        }
    };
    auto CPB = [&](int ch) {   // async-copy B chunk ch into stage ch&1
        const uint32_t bT = sb + ((ch & 1) ? SOFF_B1 : SOFF_B0);
        const size_t off = (size_t)ch * 128;   // 128B chunk inside 1024B row
        #pragma unroll
        for (int p = 0; p < 16; ++p)
            cpasync16(bT + bSt + (uint32_t)p * 16u * 128u,
                      Bsrc + (size_t)p * 16 * B_ROW_BYTES + off);
        cp_commit();
    };

    // ldmatrix constant addressing
    const uint32_t aRowBase = (uint32_t)(lane & 15);
    const uint32_t aCCoff   = (uint32_t)(lane >> 4);
    const uint32_t bRowBase = (uint32_t)(warp * 64 + (lane & 7) + ((lane >> 4) << 3));
    const uint32_t bCCoff   = (uint32_t)((lane >> 3) & 1);

    auto COMPUTE = [&](int ch) {
        const uint32_t aT = sb + ((ch & 1) ? SOFF_A1 : SOFF_A0);
        const uint32_t bT = sb + ((ch & 1) ? SOFF_B1 : SOFF_B0);
        #pragma unroll
        for (int ks = 0; ks < 4; ++ks) {
            const uint32_t ccA = (uint32_t)(ks * 2) + aCCoff;
            const uint32_t ccB = (uint32_t)(ks * 2) + bCCoff;
            uint32_t af[4][4];
            #pragma unroll
            for (int mi = 0; mi < 4; ++mi)
                ldmx4(aT + swz(aRowBase + mi * 16, ccA),
                      af[mi][0], af[mi][1], af[mi][2], af[mi][3]);
            #pragma unroll
            for (int nb = 0; nb < 4; ++nb) {
                uint32_t b0, b1, b2, b3;
                ldmx4(bT + swz(bRowBase + nb * 16, ccB), b0, b1, b2, b3);
                #pragma unroll
                for (int mi = 0; mi < 4; ++mi) {
                    mma16816(acc[mi][2 * nb + 0], af[mi], b0, b1);
                    mma16816(acc[mi][2 * nb + 1], af[mi], b2, b3);
                }
            }
        }
    };

    // -------- prologue --------
    CPB(0);
    G2R(0); R2S(0);
    G2R(1);
    cp_wait<0>();
    __syncthreads();

    // -------- mainloop: one sync per chunk; copy ch+1 runs during COMPUTE(ch) ----
    #pragma unroll 1
    for (int ch = 0; ch < NCH; ++ch) {
        if (ch + 1 < NCH) CPB(ch + 1);
        if (ch + 1 < NCH) R2S((ch + 1) & 1);
        if (ch + 2 < NCH) G2R(ch + 2);
        COMPUTE(ch);
        cp_wait<0>();
        __syncthreads();
    }

    // -------- norms --------
    float* x2s = reinterpret_cast<float*>(smem + SOFF_X2);
    float* c2s = reinterpret_cast<float*>(smem + SOFF_C2);
    #pragma unroll
    for (int p = 0; p < 8; ++p) {
        float v = nAp[p];
        v += __shfl_xor_sync(0xffffffffu, v, 1);
        v += __shfl_xor_sync(0xffffffffu, v, 2);
        v += __shfl_xor_sync(0xffffffffu, v, 4);
        v += __shfl_xor_sync(0xffffffffu, v, 8);
        if (acol == 0) x2s[arow + 8 * p] = v;
    }
    c2s[t] = g_c2[t];
    c2s[128 + t] = g_c2[128 + t];
    __syncthreads();

    // -------- epilogue pass 1: q = 1/(1+dist), row partial sums --------
    const int rbase = lane >> 2;       // 0..7
    float qs[4][2];
    #pragma unroll
    for (int mi = 0; mi < 4; ++mi) { qs[mi][0] = 0.f; qs[mi][1] = 0.f; }
    #pragma unroll
    for (int mi = 0; mi < 4; ++mi) {
        const float x2a = x2s[rbase + mi * 16];
        const float x2b = x2s[rbase + mi * 16 + 8];
        #pragma unroll
        for (int ni = 0; ni < 8; ++ni) {
            const int col = warp * 64 + ni * 8 + (lane & 3) * 2;
            const float c2a = c2s[col], c2b = c2s[col + 1];
            float q0 = __fdividef(1.f, 1.f + fmaxf(x2a + c2a - 2.f * acc[mi][ni][0], 0.f));
            float q1 = __fdividef(1.f, 1.f + fmaxf(x2a + c2b - 2.f * acc[mi][ni][1], 0.f));
            float q2 = __fdividef(1.f, 1.f + fmaxf(x2b + c2a - 2.f * acc[mi][ni][2], 0.f));
            float q3 = __fdividef(1.f, 1.f + fmaxf(x2b + c2b - 2.f * acc[mi][ni][3], 0.f));
            acc[mi][ni][0] = q0; acc[mi][ni][1] = q1;
            acc[mi][ni][2] = q2; acc[mi][ni][3] = q3;
            qs[mi][0] += q0 + q1;
            qs[mi][1] += q2 + q3;
        }
    }
    float* rs = reinterpret_cast<float*>(smem + SOFF_RS);
    #pragma unroll
    for (int mi = 0; mi < 4; ++mi) {
        #pragma unroll
        for (int h = 0; h < 2; ++h) {
            float v = qs[mi][h];
            v += __shfl_xor_sync(0xffffffffu, v, 1);
            v += __shfl_xor_sync(0xffffffffu, v, 2);
            if ((lane & 3) == 0)
                rs[warp * 64 + rbase + mi * 16 + h * 8] = v;
        }
    }
    __syncthreads();

    // -------- epilogue pass 2: scale + store --------
    #pragma unroll
    for (int mi = 0; mi < 4; ++mi) {
        #pragma unroll
        for (int h = 0; h < 2; ++h) {
            const int r = rbase + mi * 16 + h * 8;
            const float inv = __fdividef(1.f,
                rs[r] + rs[64 + r] + rs[128 + r] + rs[192 + r]);
            float* orow = Out + (size_t)(m0 + r) * KCL + warp * 64 + (lane & 3) * 2;
            #pragma unroll
            for (int ni = 0; ni < 8; ++ni) {
                float2 v;
                v.x = acc[mi][ni][2 * h + 0] * inv;
                v.y = acc[mi][ni][2 * h + 1] * inv;
                *reinterpret_cast<float2*>(orow + ni * 8) = v;
            }
        }
    }
}

extern "C" void kernel_launch(void* const* d_in, const int* in_sizes, int n_in,
                              void* d_out, int out_size)
{
    const float* X  = (const float*)d_in[0];
    const float* Cc = (const float*)d_in[1];
    if (n_in >= 2 && in_sizes[0] < in_sizes[1]) {   // X is the big tensor
        const float* tmp = X; X = Cc; Cc = tmp;
    }
    float* Out = (float*)d_out;

    static int smem_set = 0;
    if (!smem_set) {
        cudaFuncSetAttribute(cluster_q_kernel,
                             cudaFuncAttributeMaxDynamicSharedMemorySize, SMEM_BYTES);
        smem_set = 1;
    }
    conv_b_kernel<<<KCL, 128>>>(Cc);
    cluster_q_kernel<<<NROWS / BM, 128, SMEM_BYTES>>>(X, Out);
}